// round 1
// baseline (speedup 1.0000x reference)
#include <cuda_runtime.h>
#include <math.h>

#define N_NODES 100000
#define N_EDGES 1600000
#define D_HID 128
#define D_OUT 32

// ---------------- scratch (static device allocations; allowed) ----------------
__device__ float g_yl[(size_t)N_NODES * D_HID];   // x @ Wl  (also reused for layer2, 32-wide)
__device__ float g_yr[(size_t)N_NODES * D_HID];   // x @ Wr
__device__ float g_acc[(size_t)N_NODES * D_HID];  // scatter accumulator
__device__ float g_h0[(size_t)N_NODES * D_HID];   // layer0 output
__device__ float g_h1[(size_t)N_NODES * D_HID];   // layer1 output
__device__ float g_deg[N_NODES];                  // degree -> reciprocal degree
__device__ int   g_idx64;                         // 1 if edge_index is int64, 0 if int32

// ---------------- edge index dtype detection ----------------
// If edge_index is int64 (values < 2^32), every odd 32-bit word of the buffer is 0.
// If it is int32, odd words are random src values in [0, 100000) -> ~never all zero.
__global__ void detect_idx_kernel(const int* __restrict__ ei32) {
    if (blockIdx.x == 0 && threadIdx.x == 0) {
        int all0 = 1;
#pragma unroll
        for (int i = 1; i < 64; i += 2) all0 &= (ei32[i] == 0);
        g_idx64 = all0;
    }
}

__device__ __forceinline__ int2 load_edge(const void* __restrict__ ei, int e) {
    int2 r;
    if (g_idx64) {
        const long long* p = (const long long*)ei;
        r.x = (int)p[e];
        r.y = (int)p[N_EDGES + e];
    } else {
        const int* p = (const int*)ei;
        r.x = p[e];
        r.y = p[N_EDGES + e];
    }
    return r;
}

// ---------------- degree ----------------
__global__ void zero_deg_kernel() {
    int i = blockIdx.x * blockDim.x + threadIdx.x;
    if (i < N_NODES) g_deg[i] = 0.f;
}

__global__ void deg_kernel(const void* __restrict__ ei) {
    int e = blockIdx.x * blockDim.x + threadIdx.x;
    if (e >= N_EDGES) return;
    int d;
    if (g_idx64) d = (int)((const long long*)ei)[N_EDGES + e];
    else         d = ((const int*)ei)[N_EDGES + e];
    atomicAdd(&g_deg[d], 1.0f);
}

__global__ void invdeg_kernel() {
    int i = blockIdx.x * blockDim.x + threadIdx.x;
    if (i < N_NODES) g_deg[i] = 1.0f / fmaxf(g_deg[i], 1.0f);
}

__global__ void zero_acc_kernel(int n4) {
    int i = blockIdx.x * blockDim.x + threadIdx.x;
    if (i < n4) ((float4*)g_acc)[i] = make_float4(0.f, 0.f, 0.f, 0.f);
}

// ---------------- GEMM: Y[N x DO] = X[N x 128] @ W[128 x DO] ----------------
// BM=64, BN=DO, full K=128 resident in smem. A tile stored transposed (Xs[k][m])
// so the inner-loop A reads are warp-uniform broadcasts; B reads (Ws[k][tx*TN])
// are 512B clean quarter-warp wavefronts.
template <int DO>
__launch_bounds__(256, 2)
__global__ void gemm_kernel(const float* __restrict__ X, const float* __restrict__ W,
                            float* __restrict__ Y) {
    constexpr int TN = DO / 32;  // 4 for DO=128, 1 for DO=32
    extern __shared__ float sm[];
    float* Xs = sm;               // [128][64] (k-major, transposed)
    float* Ws = sm + 128 * 64;    // [128][DO]

    const int t  = threadIdx.x;
    const int m0 = blockIdx.x * 64;

    // Load A tile (64 x 128) transposed into Xs
#pragma unroll
    for (int i = 0; i < 8; ++i) {
        int idx = t + i * 256;        // 0..2047 float4 slots
        int r   = idx >> 5;           // tile row 0..63
        int kc  = (idx & 31) << 2;    // k column 0..124
        int gr  = m0 + r;
        float4 v = make_float4(0.f, 0.f, 0.f, 0.f);
        if (gr < N_NODES) v = *(const float4*)(X + (size_t)gr * 128 + kc);
        Xs[(kc + 0) * 64 + r] = v.x;
        Xs[(kc + 1) * 64 + r] = v.y;
        Xs[(kc + 2) * 64 + r] = v.z;
        Xs[(kc + 3) * 64 + r] = v.w;
    }
    // Load full W (128 x DO)
    for (int i = t; i < 128 * DO / 4; i += 256)
        ((float4*)Ws)[i] = ((const float4*)W)[i];
    __syncthreads();

    const int tx = t & 31;   // lane -> output column group
    const int ty = t >> 5;   // warp -> 8-row group

    float acc[8][TN];
#pragma unroll
    for (int i = 0; i < 8; ++i)
#pragma unroll
        for (int j = 0; j < TN; ++j) acc[i][j] = 0.f;

#pragma unroll 8
    for (int k = 0; k < 128; ++k) {
        float4 a0 = *(const float4*)(Xs + k * 64 + ty * 8);
        float4 a1 = *(const float4*)(Xs + k * 64 + ty * 8 + 4);
        float a[8] = {a0.x, a0.y, a0.z, a0.w, a1.x, a1.y, a1.z, a1.w};
        float b[TN];
        if constexpr (TN == 4) {
            float4 bv = *(const float4*)(Ws + k * DO + tx * 4);
            b[0] = bv.x; b[1] = bv.y; b[2] = bv.z; b[3] = bv.w;
        } else {
            b[0] = Ws[k * DO + tx];
        }
#pragma unroll
        for (int i = 0; i < 8; ++i)
#pragma unroll
            for (int j = 0; j < TN; ++j)
                acc[i][j] = fmaf(a[i], b[j], acc[i][j]);
    }

#pragma unroll
    for (int i = 0; i < 8; ++i) {
        int gr = m0 + ty * 8 + i;
        if (gr < N_NODES) {
            if constexpr (TN == 4) {
                float4 o = make_float4(acc[i][0], acc[i][1], acc[i][2], acc[i][3]);
                *(float4*)(Y + (size_t)gr * DO + tx * 4) = o;
            } else {
                Y[(size_t)gr * DO + tx] = acc[i][0];
            }
        }
    }
}

// ---------------- scatter (aggregation) ----------------
// One warp per edge: 32 lanes x float4 = full 128-float row.
__global__ void scatter128_kernel(const float* __restrict__ Y, const void* __restrict__ ei) {
    int gid  = blockIdx.x * blockDim.x + threadIdx.x;
    int e    = gid >> 5;
    if (e >= N_EDGES) return;
    int lane = threadIdx.x & 31;
    int2 sd  = load_edge(ei, e);
    float4 v = *(const float4*)(Y + (size_t)sd.x * 128 + lane * 4);
    float* p = g_acc + (size_t)sd.y * 128 + lane * 4;
    atomicAdd(p + 0, v.x);
    atomicAdd(p + 1, v.y);
    atomicAdd(p + 2, v.z);
    atomicAdd(p + 3, v.w);
}

// 8 threads per edge for the 32-wide layer.
__global__ void scatter32_kernel(const float* __restrict__ Y, const void* __restrict__ ei) {
    int gid = blockIdx.x * blockDim.x + threadIdx.x;
    int e   = gid >> 3;
    if (e >= N_EDGES) return;
    int c   = gid & 7;
    int2 sd = load_edge(ei, e);
    float4 v = *(const float4*)(Y + (size_t)sd.x * 32 + c * 4);
    float* p = g_acc + (size_t)sd.y * 32 + c * 4;
    atomicAdd(p + 0, v.x);
    atomicAdd(p + 1, v.y);
    atomicAdd(p + 2, v.z);
    atomicAdd(p + 3, v.w);
}

// ---------------- epilogues ----------------
// h = relu(acc * invdeg + bl + yr)   (over N x 128, float4 granularity)
__global__ void finalize_relu_kernel(const float* __restrict__ bl, float* __restrict__ h) {
    int i = blockIdx.x * blockDim.x + threadIdx.x;  // over N*32 float4
    if (i >= N_NODES * 32) return;
    int node = i >> 5;
    int f4   = i & 31;
    float id = g_deg[node];
    float4 a = ((const float4*)g_acc)[i];
    float4 r = ((const float4*)g_yr)[i];
    float4 b = ((const float4*)bl)[f4];
    float4 o;
    o.x = fmaxf(fmaf(a.x, id, b.x) + r.x, 0.f);
    o.y = fmaxf(fmaf(a.y, id, b.y) + r.y, 0.f);
    o.z = fmaxf(fmaf(a.z, id, b.z) + r.z, 0.f);
    o.w = fmaxf(fmaf(a.w, id, b.w) + r.w, 0.f);
    ((float4*)h)[i] = o;
}

// out = log_softmax(acc * invdeg + bl2 + yr) over 32 classes; one warp per node.
__global__ void lsm_kernel(const float* __restrict__ bl2, float* __restrict__ out) {
    int gid  = blockIdx.x * blockDim.x + threadIdx.x;
    int node = gid >> 5;
    if (node >= N_NODES) return;
    int lane = threadIdx.x & 31;
    size_t idx = (size_t)node * 32 + lane;
    float v = fmaf(g_acc[idx], g_deg[node], bl2[lane]) + g_yr[idx];
    float m = v;
#pragma unroll
    for (int o = 16; o; o >>= 1) m = fmaxf(m, __shfl_xor_sync(0xFFFFFFFFu, m, o));
    float ex = expf(v - m);
    float s = ex;
#pragma unroll
    for (int o = 16; o; o >>= 1) s += __shfl_xor_sync(0xFFFFFFFFu, s, o);
    out[idx] = v - m - logf(s);
}

// ---------------- host ----------------
extern "C" void kernel_launch(void* const* d_in, const int* in_sizes, int n_in,
                              void* d_out, int out_size) {
    const float* x   = (const float*)d_in[0];
    const void*  ei  = d_in[1];
    const float* Wl0 = (const float*)d_in[2];
    const float* bl0 = (const float*)d_in[3];
    const float* Wr0 = (const float*)d_in[4];
    const float* Wl1 = (const float*)d_in[5];
    const float* bl1 = (const float*)d_in[6];
    const float* Wr1 = (const float*)d_in[7];
    const float* Wl2 = (const float*)d_in[8];
    const float* bl2 = (const float*)d_in[9];
    const float* Wr2 = (const float*)d_in[10];
    float* out = (float*)d_out;

    float *yl, *yr, *h0, *h1;
    cudaGetSymbolAddress((void**)&yl, g_yl);
    cudaGetSymbolAddress((void**)&yr, g_yr);
    cudaGetSymbolAddress((void**)&h0, g_h0);
    cudaGetSymbolAddress((void**)&h1, g_h1);

    cudaFuncSetAttribute(gemm_kernel<128>, cudaFuncAttributeMaxDynamicSharedMemorySize, 98304);
    cudaFuncSetAttribute(gemm_kernel<32>,  cudaFuncAttributeMaxDynamicSharedMemorySize, 49152);

    const int T = 256;
    const int GB = (N_NODES + 63) / 64;

    detect_idx_kernel<<<1, 32>>>((const int*)ei);
    zero_deg_kernel<<<(N_NODES + T - 1) / T, T>>>();
    deg_kernel<<<(N_EDGES + T - 1) / T, T>>>(ei);
    invdeg_kernel<<<(N_NODES + T - 1) / T, T>>>();

    // ---- Layer 0 ----
    gemm_kernel<128><<<GB, T, 98304>>>(x, Wl0, yl);
    gemm_kernel<128><<<GB, T, 98304>>>(x, Wr0, yr);
    zero_acc_kernel<<<(N_NODES * 32 + T - 1) / T, T>>>(N_NODES * 32);
    scatter128_kernel<<<(N_EDGES * 32 + T - 1) / T, T>>>(yl, ei);
    finalize_relu_kernel<<<(N_NODES * 32 + T - 1) / T, T>>>(bl0, h0);

    // ---- Layer 1 ----
    gemm_kernel<128><<<GB, T, 98304>>>(h0, Wl1, yl);
    gemm_kernel<128><<<GB, T, 98304>>>(h0, Wr1, yr);
    zero_acc_kernel<<<(N_NODES * 32 + T - 1) / T, T>>>(N_NODES * 32);
    scatter128_kernel<<<(N_EDGES * 32 + T - 1) / T, T>>>(yl, ei);
    finalize_relu_kernel<<<(N_NODES * 32 + T - 1) / T, T>>>(bl1, h1);

    // ---- Layer 2 ----
    gemm_kernel<32><<<GB, T, 49152>>>(h1, Wl2, yl);
    gemm_kernel<32><<<GB, T, 49152>>>(h1, Wr2, yr);
    zero_acc_kernel<<<(N_NODES * 8 + T - 1) / T, T>>>(N_NODES * 8);
    scatter32_kernel<<<(N_EDGES * 8 + T - 1) / T, T>>>(yl, ei);
    lsm_kernel<<<(N_NODES * 32 + T - 1) / T, T>>>(bl2, out);
}

// round 3
// speedup vs baseline: 3.6923x; 3.6923x over previous
#include <cuda_runtime.h>
#include <math.h>
#include <stdint.h>

#define N_NODES 100000
#define N_EDGES 1600000
#define D_HID 128
#define D_OUT 32
#define SCAN_B 1024

// ---------------- scratch ----------------
__device__ float g_yl[(size_t)N_NODES * D_HID];
__device__ float g_yr[(size_t)N_NODES * D_HID];
__device__ float g_h0[(size_t)N_NODES * D_HID];
__device__ float g_invdeg[N_NODES];
__device__ int   g_cnt[N_NODES];
__device__ int   g_rowptr[N_NODES + 1];
__device__ int   g_fill[N_NODES];
__device__ int   g_srcs[N_EDGES];
__device__ int   g_bsum[(N_NODES + SCAN_B - 1) / SCAN_B];
__device__ int   g_boff[(N_NODES + SCAN_B - 1) / SCAN_B];
__device__ int   g_idx64;

// ---------------- helpers ----------------
__device__ __forceinline__ uint32_t f2tf32(float f) {
    uint32_t r;
    asm("cvt.rna.tf32.f32 %0, %1;" : "=r"(r) : "f"(f));
    return r;
}
__device__ __forceinline__ void mma_tf32(float c[4], const uint32_t a[4], const uint32_t b[2]) {
    asm volatile(
        "mma.sync.aligned.m16n8k8.row.col.f32.tf32.tf32.f32 "
        "{%0,%1,%2,%3}, {%4,%5,%6,%7}, {%8,%9}, {%0,%1,%2,%3};"
        : "+f"(c[0]), "+f"(c[1]), "+f"(c[2]), "+f"(c[3])
        : "r"(a[0]), "r"(a[1]), "r"(a[2]), "r"(a[3]), "r"(b[0]), "r"(b[1]));
}

// ---------------- edge index dtype detection ----------------
__global__ void detect_idx_kernel(const int* __restrict__ ei32) {
    if (blockIdx.x == 0 && threadIdx.x == 0) {
        int all0 = 1;
#pragma unroll
        for (int i = 1; i < 64; i += 2) all0 &= (ei32[i] == 0);
        g_idx64 = all0;
    }
}
__device__ __forceinline__ int edge_src(const void* __restrict__ ei, int e) {
    return g_idx64 ? (int)((const long long*)ei)[e] : ((const int*)ei)[e];
}
__device__ __forceinline__ int edge_dst(const void* __restrict__ ei, int e) {
    return g_idx64 ? (int)((const long long*)ei)[N_EDGES + e] : ((const int*)ei)[N_EDGES + e];
}

// ---------------- CSR build ----------------
__global__ void zero_cnt_kernel() {
    int i = blockIdx.x * blockDim.x + threadIdx.x;
    if (i < N_NODES) g_cnt[i] = 0;
}
__global__ void hist_kernel(const void* __restrict__ ei) {
    int e = blockIdx.x * blockDim.x + threadIdx.x;
    if (e < N_EDGES) atomicAdd(&g_cnt[edge_dst(ei, e)], 1);
}
// inclusive block scan of g_cnt; writes rowptr[i+1] (pre-offset), block sums.
__global__ void scan_block_kernel() {
    __shared__ int sb[2][SCAN_B];
    int tid = threadIdx.x;
    int i = blockIdx.x * SCAN_B + tid;
    int v = (i < N_NODES) ? g_cnt[i] : 0;
    sb[0][tid] = v;
    int cur = 0;
#pragma unroll
    for (int d = 1; d < SCAN_B; d <<= 1) {
        __syncthreads();
        int nv = sb[cur][tid] + (tid >= d ? sb[cur][tid - d] : 0);
        sb[cur ^ 1][tid] = nv;
        cur ^= 1;
    }
    __syncthreads();
    if (i < N_NODES) g_rowptr[i + 1] = sb[cur][tid];
    if (tid == SCAN_B - 1) g_bsum[blockIdx.x] = sb[cur][tid];
    if (i == 0) g_rowptr[0] = 0;
}
__global__ void scan_bsum_kernel(int nblocks) {
    if (threadIdx.x == 0) {
        int run = 0;
        for (int b = 0; b < nblocks; ++b) { g_boff[b] = run; run += g_bsum[b]; }
    }
}
// apply offsets, compute invdeg and fill pointers
__global__ void finalize_csr_kernel() {
    int i = blockIdx.x * blockDim.x + threadIdx.x;
    if (i >= N_NODES) return;
    int off = g_boff[i / SCAN_B];
    int end = g_rowptr[i + 1] + off;
    g_rowptr[i + 1] = end;
    int c = g_cnt[i];
    g_fill[i] = end - c;
    g_invdeg[i] = 1.0f / fmaxf((float)c, 1.0f);
}
__global__ void fill_kernel(const void* __restrict__ ei) {
    int e = blockIdx.x * blockDim.x + threadIdx.x;
    if (e >= N_EDGES) return;
    int d = edge_dst(ei, e);
    int pos = atomicAdd(&g_fill[d], 1);
    g_srcs[pos] = edge_src(ei, e);
}

// ---------------- GEMM: Y[N x DO] = X[N x 128] @ W[128 x DO] (tf32 mma.sync) ----------------
// DO=128: CTA = 64 rows, 8 warps = 4(m) x 2(n), warp tile 16 x 64 (8 n8-tiles)
// DO=32 : CTA = 128 rows, 8 warps = 8(m) x 1(n), warp tile 16 x 32 (4 n8-tiles)
template <int DO>
__launch_bounds__(256, 2)
__global__ void gemm_kernel(const float* __restrict__ X,
                            const float* __restrict__ Wl, const float* __restrict__ Wr,
                            float* __restrict__ Yl, float* __restrict__ Yr) {
    constexpr int NWM = (DO == 128) ? 4 : 8;       // warps along m
    constexpr int NT  = (DO == 128) ? 8 : 4;       // n8-tiles per warp
    constexpr int MROWS = NWM * 16;                // CTA rows
    constexpr int SA = 132;                        // A row stride (floats, padded)
    constexpr int SB = DO + 4;                     // B row stride (floats, padded)

    extern __shared__ uint32_t sm[];
    uint32_t* As = sm;                 // [MROWS][SA]
    uint32_t* Bs = sm + MROWS * SA;    // [128][SB]

    const float* W = blockIdx.y ? Wr : Wl;
    float* Y       = blockIdx.y ? Yr : Yl;

    const int t = threadIdx.x;
    const int w = t >> 5;
    const int lane = t & 31;
    const int g = lane >> 2;           // groupID 0..7
    const int tg = lane & 3;           // thread-in-group 0..3
    const int m0 = blockIdx.x * MROWS;

    // ---- load A tile (MROWS x 128), convert to tf32, zero-fill OOB ----
#pragma unroll
    for (int it = 0; it < MROWS * 32 / 256; ++it) {
        int idx = t + it * 256;        // float4 slots
        int row = idx >> 5;
        int c4  = idx & 31;
        int gr  = m0 + row;
        float4 v = make_float4(0.f, 0.f, 0.f, 0.f);
        if (gr < N_NODES) v = *(const float4*)(X + (size_t)gr * 128 + c4 * 4);
        uint32_t* p = As + row * SA + c4 * 4;
        p[0] = f2tf32(v.x); p[1] = f2tf32(v.y); p[2] = f2tf32(v.z); p[3] = f2tf32(v.w);
    }
    // ---- load B = W (128 x DO), convert ----
#pragma unroll
    for (int it = 0; it < 128 * DO / 4 / 256; ++it) {
        int i4 = t + it * 256;
        int k  = i4 / (DO / 4);
        int c4 = i4 % (DO / 4);
        float4 v = ((const float4*)W)[i4];
        uint32_t* p = Bs + k * SB + c4 * 4;
        p[0] = f2tf32(v.x); p[1] = f2tf32(v.y); p[2] = f2tf32(v.z); p[3] = f2tf32(v.w);
    }
    __syncthreads();

    const int mi = (DO == 128) ? (w & 3) : w;
    const int ni = (DO == 128) ? (w >> 2) : 0;
    const int mr = mi * 16;
    const int nb = ni * 64;

    float acc[NT][4];
#pragma unroll
    for (int n = 0; n < NT; ++n)
#pragma unroll
        for (int q = 0; q < 4; ++q) acc[n][q] = 0.f;

#pragma unroll
    for (int kt = 0; kt < 16; ++kt) {
        const int k0 = kt * 8;
        uint32_t a[4];
        a[0] = As[(mr + g)     * SA + k0 + tg];
        a[1] = As[(mr + g + 8) * SA + k0 + tg];
        a[2] = As[(mr + g)     * SA + k0 + tg + 4];
        a[3] = As[(mr + g + 8) * SA + k0 + tg + 4];
#pragma unroll
        for (int n = 0; n < NT; ++n) {
            uint32_t b[2];
            int col = nb + n * 8 + g;
            b[0] = Bs[(k0 + tg)     * SB + col];
            b[1] = Bs[(k0 + tg + 4) * SB + col];
            mma_tf32(acc[n], a, b);
        }
    }

    // ---- epilogue ----
    const int r0 = m0 + mr + g;
    const int r1 = r0 + 8;
#pragma unroll
    for (int n = 0; n < NT; ++n) {
        int col = nb + n * 8 + 2 * tg;
        if (r0 < N_NODES) *(float2*)(Y + (size_t)r0 * DO + col) = make_float2(acc[n][0], acc[n][1]);
        if (r1 < N_NODES) *(float2*)(Y + (size_t)r1 * DO + col) = make_float2(acc[n][2], acc[n][3]);
    }
}

// ---------------- aggregation (CSR gather) + fused epilogue ----------------
// h = relu(mean_{s in N(i)} yl[s] + bl + yr[i]); one warp per node, lane = float4 slice
__global__ void agg_relu_kernel(const float* __restrict__ yl, const float* __restrict__ yr,
                                const float* __restrict__ bl, float* __restrict__ h) {
    int node = blockIdx.x * (blockDim.x >> 5) + (threadIdx.x >> 5);
    if (node >= N_NODES) return;
    int lane = threadIdx.x & 31;
    int beg = g_rowptr[node], end = g_rowptr[node + 1];
    float4 acc = make_float4(0.f, 0.f, 0.f, 0.f);
    int j = beg;
    for (; j + 2 <= end; j += 2) {
        int s0 = __ldg(&g_srcs[j]);
        int s1 = __ldg(&g_srcs[j + 1]);
        float4 v0 = *(const float4*)(yl + (size_t)s0 * 128 + lane * 4);
        float4 v1 = *(const float4*)(yl + (size_t)s1 * 128 + lane * 4);
        acc.x += v0.x + v1.x; acc.y += v0.y + v1.y;
        acc.z += v0.z + v1.z; acc.w += v0.w + v1.w;
    }
    if (j < end) {
        int s = __ldg(&g_srcs[j]);
        float4 v = *(const float4*)(yl + (size_t)s * 128 + lane * 4);
        acc.x += v.x; acc.y += v.y; acc.z += v.z; acc.w += v.w;
    }
    float id = g_invdeg[node];
    float4 r = ((const float4*)yr)[(size_t)node * 32 + lane];
    float4 b = ((const float4*)bl)[lane];
    float4 o;
    o.x = fmaxf(fmaf(acc.x, id, b.x) + r.x, 0.f);
    o.y = fmaxf(fmaf(acc.y, id, b.y) + r.y, 0.f);
    o.z = fmaxf(fmaf(acc.z, id, b.z) + r.z, 0.f);
    o.w = fmaxf(fmaf(acc.w, id, b.w) + r.w, 0.f);
    ((float4*)h)[(size_t)node * 32 + lane] = o;
}

// out = log_softmax(mean_gather(yl) + bl2 + yr) over 32 classes; one warp per node
__global__ void agg_lsm_kernel(const float* __restrict__ yl, const float* __restrict__ yr,
                               const float* __restrict__ bl2, float* __restrict__ out) {
    int node = blockIdx.x * (blockDim.x >> 5) + (threadIdx.x >> 5);
    if (node >= N_NODES) return;
    int lane = threadIdx.x & 31;
    int beg = g_rowptr[node], end = g_rowptr[node + 1];
    float acc = 0.f;
    int j = beg;
    for (; j + 2 <= end; j += 2) {
        int s0 = __ldg(&g_srcs[j]);
        int s1 = __ldg(&g_srcs[j + 1]);
        acc += __ldg(yl + (size_t)s0 * 32 + lane) + __ldg(yl + (size_t)s1 * 32 + lane);
    }
    if (j < end) acc += __ldg(yl + (size_t)__ldg(&g_srcs[j]) * 32 + lane);
    float v = fmaf(acc, g_invdeg[node], bl2[lane]) + yr[(size_t)node * 32 + lane];
    float m = v;
#pragma unroll
    for (int o = 16; o; o >>= 1) m = fmaxf(m, __shfl_xor_sync(0xFFFFFFFFu, m, o));
    float ex = expf(v - m);
    float s = ex;
#pragma unroll
    for (int o = 16; o; o >>= 1) s += __shfl_xor_sync(0xFFFFFFFFu, s, o);
    out[(size_t)node * 32 + lane] = v - m - logf(s);
}

// ---------------- host ----------------
extern "C" void kernel_launch(void* const* d_in, const int* in_sizes, int n_in,
                              void* d_out, int out_size) {
    const float* x   = (const float*)d_in[0];
    const void*  ei  = d_in[1];
    const float* Wl0 = (const float*)d_in[2];
    const float* bl0 = (const float*)d_in[3];
    const float* Wr0 = (const float*)d_in[4];
    const float* Wl1 = (const float*)d_in[5];
    const float* bl1 = (const float*)d_in[6];
    const float* Wr1 = (const float*)d_in[7];
    const float* Wl2 = (const float*)d_in[8];
    const float* bl2 = (const float*)d_in[9];
    const float* Wr2 = (const float*)d_in[10];
    float* out = (float*)d_out;

    float *yl, *yr, *h0;
    cudaGetSymbolAddress((void**)&yl, g_yl);
    cudaGetSymbolAddress((void**)&yr, g_yr);
    cudaGetSymbolAddress((void**)&h0, g_h0);

    const int SMEM128 = (64 * 132 + 128 * 132) * 4;   // 101376
    const int SMEM32  = (128 * 132 + 128 * 36) * 4;   // 86016
    cudaFuncSetAttribute(gemm_kernel<128>, cudaFuncAttributeMaxDynamicSharedMemorySize, SMEM128);
    cudaFuncSetAttribute(gemm_kernel<32>,  cudaFuncAttributeMaxDynamicSharedMemorySize, SMEM32);

    const int T = 256;
    const int NB = (N_NODES + T - 1) / T;
    const int EB = (N_EDGES + T - 1) / T;
    const int SCB = (N_NODES + SCAN_B - 1) / SCAN_B;   // 98
    const int WARPS_PER_BLK = T / 32;
    const int AGG_B = (N_NODES + WARPS_PER_BLK - 1) / WARPS_PER_BLK;
    dim3 g128((N_NODES + 63) / 64, 2);
    dim3 g32((N_NODES + 127) / 128, 2);

    // launches 1-5 (CSR front half), #6 = layer-0 GEMM (ncu -s 5 -c 1 capture target)
    detect_idx_kernel<<<1, 32>>>((const int*)ei);
    zero_cnt_kernel<<<NB, T>>>();
    hist_kernel<<<EB, T>>>(ei);
    scan_block_kernel<<<SCB, SCAN_B>>>();
    scan_bsum_kernel<<<1, 32>>>(SCB);

    gemm_kernel<128><<<g128, T, SMEM128>>>(x, Wl0, Wr0, yl, yr);   // #6

    finalize_csr_kernel<<<NB, T>>>();
    fill_kernel<<<EB, T>>>(ei);

    // ---- Layer 0 aggregation ----
    agg_relu_kernel<<<AGG_B, T>>>(yl, yr, bl0, h0);
    // ---- Layer 1 ----
    gemm_kernel<128><<<g128, T, SMEM128>>>(h0, Wl1, Wr1, yl, yr);
    agg_relu_kernel<<<AGG_B, T>>>(yl, yr, bl1, h0);
    // ---- Layer 2 ----
    gemm_kernel<32><<<g32, T, SMEM32>>>(h0, Wl2, Wr2, yl, yr);
    agg_lsm_kernel<<<AGG_B, T>>>(yl, yr, bl2, out);
}

// round 4
// speedup vs baseline: 4.7204x; 1.2784x over previous
#include <cuda_runtime.h>
#include <cuda_bf16.h>
#include <math.h>
#include <stdint.h>

#define N_NODES 100000
#define N_EDGES 1600000
#define D_HID 128
#define D_OUT 32
#define SCAN_B 1024

// ---------------- scratch ----------------
__device__ float g_yl[(size_t)N_NODES * D_HID];   // layer2: fp32 [N,32]; layers0/1: bf16 [N,128] (aliased)
__device__ float g_yr[(size_t)N_NODES * D_HID];
__device__ float g_h0[(size_t)N_NODES * D_HID];
__device__ float g_invdeg[N_NODES];
__device__ int   g_cnt[N_NODES];
__device__ int   g_rowptr[N_NODES + 1];
__device__ int   g_fill[N_NODES];
__device__ int   g_srcs[N_EDGES];
__device__ int   g_bsum[(N_NODES + SCAN_B - 1) / SCAN_B];
__device__ int   g_boff[(N_NODES + SCAN_B - 1) / SCAN_B];
__device__ int   g_idx64;

// ---------------- helpers ----------------
__device__ __forceinline__ uint32_t f2tf32(float f) {
    uint32_t r;
    asm("cvt.rna.tf32.f32 %0, %1;" : "=r"(r) : "f"(f));
    return r;
}
__device__ __forceinline__ void mma_tf32(float c[4], const uint32_t a[4], const uint32_t b[2]) {
    asm volatile(
        "mma.sync.aligned.m16n8k8.row.col.f32.tf32.tf32.f32 "
        "{%0,%1,%2,%3}, {%4,%5,%6,%7}, {%8,%9}, {%0,%1,%2,%3};"
        : "+f"(c[0]), "+f"(c[1]), "+f"(c[2]), "+f"(c[3])
        : "r"(a[0]), "r"(a[1]), "r"(a[2]), "r"(a[3]), "r"(b[0]), "r"(b[1]));
}
__device__ __forceinline__ uint32_t pack_bf16(float a, float b) {
    __nv_bfloat162 p = __floats2bfloat162_rn(a, b);
    return *(uint32_t*)&p;
}

// ---------------- edge index dtype detection ----------------
__global__ void detect_idx_kernel(const int* __restrict__ ei32) {
    if (blockIdx.x == 0 && threadIdx.x == 0) {
        int all0 = 1;
#pragma unroll
        for (int i = 1; i < 64; i += 2) all0 &= (ei32[i] == 0);
        g_idx64 = all0;
    }
}
__device__ __forceinline__ int edge_src(const void* __restrict__ ei, int e) {
    return g_idx64 ? (int)((const long long*)ei)[e] : ((const int*)ei)[e];
}
__device__ __forceinline__ int edge_dst(const void* __restrict__ ei, int e) {
    return g_idx64 ? (int)((const long long*)ei)[N_EDGES + e] : ((const int*)ei)[N_EDGES + e];
}

// ---------------- CSR build ----------------
__global__ void zero_cnt_kernel() {
    int i = blockIdx.x * blockDim.x + threadIdx.x;
    if (i < N_NODES) g_cnt[i] = 0;
}
__global__ void hist_kernel(const void* __restrict__ ei) {
    int e = blockIdx.x * blockDim.x + threadIdx.x;
    if (e < N_EDGES) atomicAdd(&g_cnt[edge_dst(ei, e)], 1);
}
__global__ void scan_block_kernel() {
    __shared__ int sb[2][SCAN_B];
    int tid = threadIdx.x;
    int i = blockIdx.x * SCAN_B + tid;
    int v = (i < N_NODES) ? g_cnt[i] : 0;
    sb[0][tid] = v;
    int cur = 0;
#pragma unroll
    for (int d = 1; d < SCAN_B; d <<= 1) {
        __syncthreads();
        int nv = sb[cur][tid] + (tid >= d ? sb[cur][tid - d] : 0);
        sb[cur ^ 1][tid] = nv;
        cur ^= 1;
    }
    __syncthreads();
    if (i < N_NODES) g_rowptr[i + 1] = sb[cur][tid];
    if (tid == SCAN_B - 1) g_bsum[blockIdx.x] = sb[cur][tid];
    if (i == 0) g_rowptr[0] = 0;
}
__global__ void scan_bsum_kernel(int nblocks) {
    if (threadIdx.x == 0) {
        int run = 0;
        for (int b = 0; b < nblocks; ++b) { g_boff[b] = run; run += g_bsum[b]; }
    }
}
__global__ void finalize_csr_kernel() {
    int i = blockIdx.x * blockDim.x + threadIdx.x;
    if (i >= N_NODES) return;
    int off = g_boff[i / SCAN_B];
    int end = g_rowptr[i + 1] + off;
    g_rowptr[i + 1] = end;
    int c = g_cnt[i];
    g_fill[i] = end - c;
    g_invdeg[i] = 1.0f / fmaxf((float)c, 1.0f);
}
__global__ void fill_kernel(const void* __restrict__ ei) {
    int e = blockIdx.x * blockDim.x + threadIdx.x;
    if (e >= N_EDGES) return;
    int d = edge_dst(ei, e);
    int pos = atomicAdd(&g_fill[d], 1);
    g_srcs[pos] = edge_src(ei, e);
}

// ---------------- dual GEMM, DO=128: Yl(bf16) = X@Wl, Yr(fp32) = X@Wr ----------------
// 512 threads, 16 warps = 8(m) x 2(n); warp tile 16x64; 128-row CTA tile; K=128 resident.
__launch_bounds__(512, 1)
__global__ void gemm128_dual_kernel(const float* __restrict__ X,
                                    const float* __restrict__ Wl, const float* __restrict__ Wr,
                                    __nv_bfloat16* __restrict__ Ylb, float* __restrict__ Yr) {
    constexpr int SA = 132, SB = 136;
    extern __shared__ uint32_t sm[];
    uint32_t* As  = sm;                       // [128][SA]
    uint32_t* Bls = sm + 128 * SA;            // [128][SB]
    uint32_t* Brs = Bls + 128 * SB;

    const int t = threadIdx.x;
    const int w = t >> 5;
    const int lane = t & 31;
    const int g = lane >> 2, tg = lane & 3;
    const int m0 = blockIdx.x * 128;

    // A tile (128 x 128)
#pragma unroll
    for (int it = 0; it < 8; ++it) {
        int idx = t + it * 512;
        int row = idx >> 5, c4 = idx & 31;
        int gr  = m0 + row;
        float4 v = make_float4(0.f, 0.f, 0.f, 0.f);
        if (gr < N_NODES) v = *(const float4*)(X + (size_t)gr * 128 + c4 * 4);
        uint32_t* p = As + row * SA + c4 * 4;
        p[0] = f2tf32(v.x); p[1] = f2tf32(v.y); p[2] = f2tf32(v.z); p[3] = f2tf32(v.w);
    }
    // B tiles (128 x 128 each)
#pragma unroll
    for (int it = 0; it < 8; ++it) {
        int i4 = t + it * 512;
        int k = i4 >> 5, c4 = i4 & 31;
        float4 vl = ((const float4*)Wl)[i4];
        float4 vr = ((const float4*)Wr)[i4];
        uint32_t* pl = Bls + k * SB + c4 * 4;
        uint32_t* pr = Brs + k * SB + c4 * 4;
        pl[0] = f2tf32(vl.x); pl[1] = f2tf32(vl.y); pl[2] = f2tf32(vl.z); pl[3] = f2tf32(vl.w);
        pr[0] = f2tf32(vr.x); pr[1] = f2tf32(vr.y); pr[2] = f2tf32(vr.z); pr[3] = f2tf32(vr.w);
    }
    __syncthreads();

    const int mr = (w & 7) * 16;
    const int nb = (w >> 3) * 64;

    float accl[8][4], accr[8][4];
#pragma unroll
    for (int n = 0; n < 8; ++n)
#pragma unroll
        for (int q = 0; q < 4; ++q) { accl[n][q] = 0.f; accr[n][q] = 0.f; }

#pragma unroll
    for (int kt = 0; kt < 16; ++kt) {
        const int k0 = kt * 8;
        uint32_t a[4];
        a[0] = As[(mr + g)     * SA + k0 + tg];
        a[1] = As[(mr + g + 8) * SA + k0 + tg];
        a[2] = As[(mr + g)     * SA + k0 + tg + 4];
        a[3] = As[(mr + g + 8) * SA + k0 + tg + 4];
#pragma unroll
        for (int n = 0; n < 8; ++n) {
            int col = nb + n * 8 + g;
            uint32_t bl[2], br[2];
            bl[0] = Bls[(k0 + tg)     * SB + col];
            bl[1] = Bls[(k0 + tg + 4) * SB + col];
            br[0] = Brs[(k0 + tg)     * SB + col];
            br[1] = Brs[(k0 + tg + 4) * SB + col];
            mma_tf32(accl[n], a, bl);
            mma_tf32(accr[n], a, br);
        }
    }

    const int r0 = m0 + mr + g;
    const int r1 = r0 + 8;
#pragma unroll
    for (int n = 0; n < 8; ++n) {
        int col = nb + n * 8 + 2 * tg;
        if (r0 < N_NODES) {
            *(uint32_t*)((char*)Ylb + (size_t)r0 * 256 + col * 2) = pack_bf16(accl[n][0], accl[n][1]);
            *(float2*)(Yr + (size_t)r0 * 128 + col) = make_float2(accr[n][0], accr[n][1]);
        }
        if (r1 < N_NODES) {
            *(uint32_t*)((char*)Ylb + (size_t)r1 * 256 + col * 2) = pack_bf16(accl[n][2], accl[n][3]);
            *(float2*)(Yr + (size_t)r1 * 128 + col) = make_float2(accr[n][2], accr[n][3]);
        }
    }
}

// ---------------- dual GEMM, DO=32 (both outputs fp32) ----------------
// 256 threads, 8 warps = 8(m) x 1(n); warp tile 16x32; 128-row CTA tile.
__launch_bounds__(256, 2)
__global__ void gemm32_dual_kernel(const float* __restrict__ X,
                                   const float* __restrict__ Wl, const float* __restrict__ Wr,
                                   float* __restrict__ Yl, float* __restrict__ Yr) {
    constexpr int SA = 132, SB = 36;
    extern __shared__ uint32_t sm[];
    uint32_t* As  = sm;                       // [128][SA]
    uint32_t* Bls = sm + 128 * SA;            // [128][SB]
    uint32_t* Brs = Bls + 128 * SB;

    const int t = threadIdx.x;
    const int w = t >> 5;
    const int lane = t & 31;
    const int g = lane >> 2, tg = lane & 3;
    const int m0 = blockIdx.x * 128;

#pragma unroll
    for (int it = 0; it < 16; ++it) {
        int idx = t + it * 256;
        int row = idx >> 5, c4 = idx & 31;
        int gr  = m0 + row;
        float4 v = make_float4(0.f, 0.f, 0.f, 0.f);
        if (gr < N_NODES) v = *(const float4*)(X + (size_t)gr * 128 + c4 * 4);
        uint32_t* p = As + row * SA + c4 * 4;
        p[0] = f2tf32(v.x); p[1] = f2tf32(v.y); p[2] = f2tf32(v.z); p[3] = f2tf32(v.w);
    }
#pragma unroll
    for (int it = 0; it < 4; ++it) {
        int i4 = t + it * 256;     // 1024 float4 slots
        int k = i4 >> 3, c4 = i4 & 7;
        float4 vl = ((const float4*)Wl)[i4];
        float4 vr = ((const float4*)Wr)[i4];
        uint32_t* pl = Bls + k * SB + c4 * 4;
        uint32_t* pr = Brs + k * SB + c4 * 4;
        pl[0] = f2tf32(vl.x); pl[1] = f2tf32(vl.y); pl[2] = f2tf32(vl.z); pl[3] = f2tf32(vl.w);
        pr[0] = f2tf32(vr.x); pr[1] = f2tf32(vr.y); pr[2] = f2tf32(vr.z); pr[3] = f2tf32(vr.w);
    }
    __syncthreads();

    const int mr = w * 16;
    float accl[4][4], accr[4][4];
#pragma unroll
    for (int n = 0; n < 4; ++n)
#pragma unroll
        for (int q = 0; q < 4; ++q) { accl[n][q] = 0.f; accr[n][q] = 0.f; }

#pragma unroll
    for (int kt = 0; kt < 16; ++kt) {
        const int k0 = kt * 8;
        uint32_t a[4];
        a[0] = As[(mr + g)     * SA + k0 + tg];
        a[1] = As[(mr + g + 8) * SA + k0 + tg];
        a[2] = As[(mr + g)     * SA + k0 + tg + 4];
        a[3] = As[(mr + g + 8) * SA + k0 + tg + 4];
#pragma unroll
        for (int n = 0; n < 4; ++n) {
            int col = n * 8 + g;
            uint32_t bl[2], br[2];
            bl[0] = Bls[(k0 + tg)     * SB + col];
            bl[1] = Bls[(k0 + tg + 4) * SB + col];
            br[0] = Brs[(k0 + tg)     * SB + col];
            br[1] = Brs[(k0 + tg + 4) * SB + col];
            mma_tf32(accl[n], a, bl);
            mma_tf32(accr[n], a, br);
        }
    }

    const int r0 = m0 + mr + g;
    const int r1 = r0 + 8;
#pragma unroll
    for (int n = 0; n < 4; ++n) {
        int col = n * 8 + 2 * tg;
        if (r0 < N_NODES) {
            *(float2*)(Yl + (size_t)r0 * 32 + col) = make_float2(accl[n][0], accl[n][1]);
            *(float2*)(Yr + (size_t)r0 * 32 + col) = make_float2(accr[n][0], accr[n][1]);
        }
        if (r1 < N_NODES) {
            *(float2*)(Yl + (size_t)r1 * 32 + col) = make_float2(accl[n][2], accl[n][3]);
            *(float2*)(Yr + (size_t)r1 * 32 + col) = make_float2(accr[n][2], accr[n][3]);
        }
    }
}

// ---------------- aggregation (CSR gather, bf16 source) + fused relu epilogue ----------------
__global__ void agg_relu_kernel(const __nv_bfloat16* __restrict__ ylb, const float* __restrict__ yr,
                                const float* __restrict__ bl, float* __restrict__ h) {
    int node = blockIdx.x * (blockDim.x >> 5) + (threadIdx.x >> 5);
    if (node >= N_NODES) return;
    int lane = threadIdx.x & 31;
    int beg = g_rowptr[node], end = g_rowptr[node + 1];
    float a0 = 0.f, a1 = 0.f, a2 = 0.f, a3 = 0.f;
    int j = beg;
    for (; j + 2 <= end; j += 2) {
        int s0 = __ldg(&g_srcs[j]);
        int s1 = __ldg(&g_srcs[j + 1]);
        uint2 u0 = *(const uint2*)((const char*)ylb + (size_t)s0 * 256 + lane * 8);
        uint2 u1 = *(const uint2*)((const char*)ylb + (size_t)s1 * 256 + lane * 8);
        float2 f0 = __bfloat1622float2(*(__nv_bfloat162*)&u0.x);
        float2 f1 = __bfloat1622float2(*(__nv_bfloat162*)&u0.y);
        float2 f2 = __bfloat1622float2(*(__nv_bfloat162*)&u1.x);
        float2 f3 = __bfloat1622float2(*(__nv_bfloat162*)&u1.y);
        a0 += f0.x + f2.x; a1 += f0.y + f2.y;
        a2 += f1.x + f3.x; a3 += f1.y + f3.y;
    }
    if (j < end) {
        int s = __ldg(&g_srcs[j]);
        uint2 u = *(const uint2*)((const char*)ylb + (size_t)s * 256 + lane * 8);
        float2 f0 = __bfloat1622float2(*(__nv_bfloat162*)&u.x);
        float2 f1 = __bfloat1622float2(*(__nv_bfloat162*)&u.y);
        a0 += f0.x; a1 += f0.y; a2 += f1.x; a3 += f1.y;
    }
    float id = g_invdeg[node];
    float4 r = ((const float4*)yr)[(size_t)node * 32 + lane];
    float4 b = ((const float4*)bl)[lane];
    float4 o;
    o.x = fmaxf(fmaf(a0, id, b.x) + r.x, 0.f);
    o.y = fmaxf(fmaf(a1, id, b.y) + r.y, 0.f);
    o.z = fmaxf(fmaf(a2, id, b.z) + r.z, 0.f);
    o.w = fmaxf(fmaf(a3, id, b.w) + r.w, 0.f);
    ((float4*)h)[(size_t)node * 32 + lane] = o;
}

// out = log_softmax(mean_gather(yl fp32) + bl2 + yr); one warp per node
__global__ void agg_lsm_kernel(const float* __restrict__ yl, const float* __restrict__ yr,
                               const float* __restrict__ bl2, float* __restrict__ out) {
    int node = blockIdx.x * (blockDim.x >> 5) + (threadIdx.x >> 5);
    if (node >= N_NODES) return;
    int lane = threadIdx.x & 31;
    int beg = g_rowptr[node], end = g_rowptr[node + 1];
    float acc = 0.f;
    int j = beg;
    for (; j + 2 <= end; j += 2) {
        int s0 = __ldg(&g_srcs[j]);
        int s1 = __ldg(&g_srcs[j + 1]);
        acc += __ldg(yl + (size_t)s0 * 32 + lane) + __ldg(yl + (size_t)s1 * 32 + lane);
    }
    if (j < end) acc += __ldg(yl + (size_t)__ldg(&g_srcs[j]) * 32 + lane);
    float v = fmaf(acc, g_invdeg[node], bl2[lane]) + yr[(size_t)node * 32 + lane];
    float m = v;
#pragma unroll
    for (int o = 16; o; o >>= 1) m = fmaxf(m, __shfl_xor_sync(0xFFFFFFFFu, m, o));
    float ex = expf(v - m);
    float s = ex;
#pragma unroll
    for (int o = 16; o; o >>= 1) s += __shfl_xor_sync(0xFFFFFFFFu, s, o);
    out[(size_t)node * 32 + lane] = v - m - logf(s);
}

// ---------------- host ----------------
extern "C" void kernel_launch(void* const* d_in, const int* in_sizes, int n_in,
                              void* d_out, int out_size) {
    const float* x   = (const float*)d_in[0];
    const void*  ei  = d_in[1];
    const float* Wl0 = (const float*)d_in[2];
    const float* bl0 = (const float*)d_in[3];
    const float* Wr0 = (const float*)d_in[4];
    const float* Wl1 = (const float*)d_in[5];
    const float* bl1 = (const float*)d_in[6];
    const float* Wr1 = (const float*)d_in[7];
    const float* Wl2 = (const float*)d_in[8];
    const float* bl2 = (const float*)d_in[9];
    const float* Wr2 = (const float*)d_in[10];
    float* out = (float*)d_out;

    float *yl, *yr, *h0;
    cudaGetSymbolAddress((void**)&yl, g_yl);
    cudaGetSymbolAddress((void**)&yr, g_yr);
    cudaGetSymbolAddress((void**)&h0, g_h0);
    __nv_bfloat16* ylb = (__nv_bfloat16*)yl;

    const int SMEM128 = (128 * 132 + 2 * 128 * 136) * 4;  // 206848
    const int SMEM32  = (128 * 132 + 2 * 128 * 36) * 4;   // 104448
    cudaFuncSetAttribute(gemm128_dual_kernel, cudaFuncAttributeMaxDynamicSharedMemorySize, SMEM128);
    cudaFuncSetAttribute(gemm32_dual_kernel,  cudaFuncAttributeMaxDynamicSharedMemorySize, SMEM32);

    const int T = 256;
    const int NB = (N_NODES + T - 1) / T;
    const int EB = (N_EDGES + T - 1) / T;
    const int SCB = (N_NODES + SCAN_B - 1) / SCAN_B;
    const int AGG_B = (N_NODES + 7) / 8;
    const int GT = (N_NODES + 127) / 128;   // 782

    // launches 1-5 = CSR front half; #6 = layer-0 GEMM (ncu -s 5 -c 1 target)
    detect_idx_kernel<<<1, 32>>>((const int*)ei);
    zero_cnt_kernel<<<NB, T>>>();
    hist_kernel<<<EB, T>>>(ei);
    scan_block_kernel<<<SCB, SCAN_B>>>();
    scan_bsum_kernel<<<1, 32>>>(SCB);

    gemm128_dual_kernel<<<GT, 512, SMEM128>>>(x, Wl0, Wr0, ylb, yr);   // #6

    finalize_csr_kernel<<<NB, T>>>();
    fill_kernel<<<EB, T>>>(ei);

    // ---- Layer 0 aggregation ----
    agg_relu_kernel<<<AGG_B, T>>>(ylb, yr, bl0, h0);
    // ---- Layer 1 ----
    gemm128_dual_kernel<<<GT, 512, SMEM128>>>(h0, Wl1, Wr1, ylb, yr);
    agg_relu_kernel<<<AGG_B, T>>>(ylb, yr, bl1, h0);
    // ---- Layer 2 ----
    gemm32_dual_kernel<<<GT, T, SMEM32>>>(h0, Wl2, Wr2, yl, yr);
    agg_lsm_kernel<<<AGG_B, T>>>(yl, yr, bl2, out);
}

// round 5
// speedup vs baseline: 5.7888x; 1.2263x over previous
#include <cuda_runtime.h>
#include <cuda_bf16.h>
#include <math.h>
#include <stdint.h>

#define N_NODES 100000
#define N_EDGES 1600000
#define D_HID 128
#define D_OUT 32
#define SCAN_B 1024

// ---------------- scratch ----------------
__device__ float g_yl[(size_t)N_NODES * D_HID];   // L0/L1: bf16 [N,128]; L2: fp32 [N,32]
__device__ float g_yr[(size_t)N_NODES * D_HID];
__device__ float g_h0[(size_t)N_NODES * D_HID];   // holds bf16 [N,128] activations
__device__ float g_invdeg[N_NODES];
__device__ int   g_cnt[N_NODES];
__device__ int   g_rowptr[N_NODES + 1];
__device__ int   g_fill[N_NODES];
__device__ int   g_srcs[N_EDGES];
__device__ int   g_bsum[(N_NODES + SCAN_B - 1) / SCAN_B];
__device__ int   g_boff[(N_NODES + SCAN_B - 1) / SCAN_B];
__device__ int   g_idx64;

// ---------------- helpers ----------------
__device__ __forceinline__ void mma_bf16(float c[4], const uint32_t a[4], const uint32_t b[2]) {
    asm volatile(
        "mma.sync.aligned.m16n8k16.row.col.f32.bf16.bf16.f32 "
        "{%0,%1,%2,%3}, {%4,%5,%6,%7}, {%8,%9}, {%0,%1,%2,%3};"
        : "+f"(c[0]), "+f"(c[1]), "+f"(c[2]), "+f"(c[3])
        : "r"(a[0]), "r"(a[1]), "r"(a[2]), "r"(a[3]), "r"(b[0]), "r"(b[1]));
}
__device__ __forceinline__ uint32_t pack_bf16(float a, float b) {
    __nv_bfloat162 p = __floats2bfloat162_rn(a, b);
    return *(uint32_t*)&p;
}

// ---------------- edge index dtype detection ----------------
__global__ void detect_idx_kernel(const int* __restrict__ ei32) {
    if (blockIdx.x == 0 && threadIdx.x == 0) {
        int all0 = 1;
#pragma unroll
        for (int i = 1; i < 64; i += 2) all0 &= (ei32[i] == 0);
        g_idx64 = all0;
    }
}
__device__ __forceinline__ int edge_src(const void* __restrict__ ei, int e) {
    return g_idx64 ? (int)((const long long*)ei)[e] : ((const int*)ei)[e];
}
__device__ __forceinline__ int edge_dst(const void* __restrict__ ei, int e) {
    return g_idx64 ? (int)((const long long*)ei)[N_EDGES + e] : ((const int*)ei)[N_EDGES + e];
}

// ---------------- CSR build ----------------
__global__ void zero_cnt_kernel() {
    int i = blockIdx.x * blockDim.x + threadIdx.x;
    if (i < N_NODES) g_cnt[i] = 0;
}
__global__ void hist_kernel(const void* __restrict__ ei) {
    int e = blockIdx.x * blockDim.x + threadIdx.x;
    if (e < N_EDGES) atomicAdd(&g_cnt[edge_dst(ei, e)], 1);
}
__global__ void scan_block_kernel() {
    __shared__ int sb[2][SCAN_B];
    int tid = threadIdx.x;
    int i = blockIdx.x * SCAN_B + tid;
    int v = (i < N_NODES) ? g_cnt[i] : 0;
    sb[0][tid] = v;
    int cur = 0;
#pragma unroll
    for (int d = 1; d < SCAN_B; d <<= 1) {
        __syncthreads();
        int nv = sb[cur][tid] + (tid >= d ? sb[cur][tid - d] : 0);
        sb[cur ^ 1][tid] = nv;
        cur ^= 1;
    }
    __syncthreads();
    if (i < N_NODES) g_rowptr[i + 1] = sb[cur][tid];
    if (tid == SCAN_B - 1) g_bsum[blockIdx.x] = sb[cur][tid];
    if (i == 0) g_rowptr[0] = 0;
}
__global__ void scan_bsum_kernel(int nblocks) {
    if (threadIdx.x == 0) {
        int run = 0;
        for (int b = 0; b < nblocks; ++b) { g_boff[b] = run; run += g_bsum[b]; }
    }
}
__global__ void finalize_csr_kernel() {
    int i = blockIdx.x * blockDim.x + threadIdx.x;
    if (i >= N_NODES) return;
    int off = g_boff[i / SCAN_B];
    int end = g_rowptr[i + 1] + off;
    g_rowptr[i + 1] = end;
    int c = g_cnt[i];
    g_fill[i] = end - c;
    g_invdeg[i] = 1.0f / fmaxf((float)c, 1.0f);
}
__global__ void fill_kernel(const void* __restrict__ ei) {
    int e = blockIdx.x * blockDim.x + threadIdx.x;
    if (e >= N_EDGES) return;
    int d = edge_dst(ei, e);
    int pos = atomicAdd(&g_fill[d], 1);
    g_srcs[pos] = edge_src(ei, e);
}

// ---------------- dual GEMM, DO=128, bf16 mma (m16n8k16) ----------------
// 512 threads, 16 warps = 8(m) x 2(n); warp tile 16x64; 128-row CTA tile; K=128 resident.
// As: [128 rows][68 u32] (bf16x2 pairs along k). B: [128 n][68 u32] (pairs along k) = W^T.
template <typename TIN>
__launch_bounds__(512, 1)
__global__ void gemm128_dual_kernel(const TIN* __restrict__ X,
                                    const float* __restrict__ Wl, const float* __restrict__ Wr,
                                    __nv_bfloat16* __restrict__ Ylb, float* __restrict__ Yr) {
    constexpr int S = 68;
    extern __shared__ uint32_t sm[];
    uint32_t* As  = sm;               // [128][68]
    uint32_t* Bls = sm + 128 * S;     // [128][68]
    uint32_t* Brs = Bls + 128 * S;

    const int t = threadIdx.x;
    const int w = t >> 5;
    const int lane = t & 31;
    const int g = lane >> 2, tg = lane & 3;
    const int m0 = blockIdx.x * 128;

    // ---- A tile ----
    if constexpr (sizeof(TIN) == 4) {   // fp32 input -> convert
#pragma unroll
        for (int it = 0; it < 8; ++it) {
            int idx = t + it * 512;
            int row = idx >> 5, c4 = idx & 31;
            int gr  = m0 + row;
            float4 v = make_float4(0.f, 0.f, 0.f, 0.f);
            if (gr < N_NODES) v = *(const float4*)((const float*)X + (size_t)gr * 128 + c4 * 4);
            uint32_t* p = As + row * S + c4 * 2;
            p[0] = pack_bf16(v.x, v.y);
            p[1] = pack_bf16(v.z, v.w);
        }
    } else {                            // bf16 input -> raw copy
#pragma unroll
        for (int it = 0; it < 4; ++it) {
            int idx = t + it * 512;     // 2048 uint4 slots
            int row = idx >> 4, q = idx & 15;
            int gr  = m0 + row;
            uint4 v = make_uint4(0, 0, 0, 0);
            if (gr < N_NODES) v = ((const uint4*)X)[(size_t)gr * 16 + q];
            *(uint4*)(As + row * S + q * 4) = v;
        }
    }
    // ---- B tiles: Bs[n][kpair] = {W[2kp][n], W[2kp+1][n]} ----
#pragma unroll
    for (int it = 0; it < 16; ++it) {
        int i = t + it * 512;           // 8192 slots
        int kp = i >> 7, n = i & 127;
        uint32_t vl = pack_bf16(Wl[(2 * kp) * 128 + n], Wl[(2 * kp + 1) * 128 + n]);
        uint32_t vr = pack_bf16(Wr[(2 * kp) * 128 + n], Wr[(2 * kp + 1) * 128 + n]);
        Bls[n * S + kp] = vl;
        Brs[n * S + kp] = vr;
    }
    __syncthreads();

    const int mr = (w & 7) * 16;
    const int nb = (w >> 3) * 64;

    float accl[8][4], accr[8][4];
#pragma unroll
    for (int n = 0; n < 8; ++n)
#pragma unroll
        for (int q = 0; q < 4; ++q) { accl[n][q] = 0.f; accr[n][q] = 0.f; }

#pragma unroll
    for (int kt = 0; kt < 8; ++kt) {
        const int kb = kt * 8;          // u32-pair offset
        uint32_t a[4];
        a[0] = As[(mr + g)     * S + kb + tg];
        a[1] = As[(mr + g + 8) * S + kb + tg];
        a[2] = As[(mr + g)     * S + kb + tg + 4];
        a[3] = As[(mr + g + 8) * S + kb + tg + 4];
#pragma unroll
        for (int n = 0; n < 8; ++n) {
            int col = nb + n * 8 + g;
            uint32_t bl[2], br[2];
            bl[0] = Bls[col * S + kb + tg];
            bl[1] = Bls[col * S + kb + tg + 4];
            br[0] = Brs[col * S + kb + tg];
            br[1] = Brs[col * S + kb + tg + 4];
            mma_bf16(accl[n], a, bl);
            mma_bf16(accr[n], a, br);
        }
    }

    const int r0 = m0 + mr + g;
    const int r1 = r0 + 8;
#pragma unroll
    for (int n = 0; n < 8; ++n) {
        int col = nb + n * 8 + 2 * tg;
        if (r0 < N_NODES) {
            *(uint32_t*)((char*)Ylb + (size_t)r0 * 256 + col * 2) = pack_bf16(accl[n][0], accl[n][1]);
            *(float2*)(Yr + (size_t)r0 * 128 + col) = make_float2(accr[n][0], accr[n][1]);
        }
        if (r1 < N_NODES) {
            *(uint32_t*)((char*)Ylb + (size_t)r1 * 256 + col * 2) = pack_bf16(accl[n][2], accl[n][3]);
            *(float2*)(Yr + (size_t)r1 * 128 + col) = make_float2(accr[n][2], accr[n][3]);
        }
    }
}

// ---------------- dual GEMM, DO=32, bf16 in, fp32 out ----------------
// 256 threads, 8 warps = 8(m) x 1(n); warp tile 16x32; 128-row CTA tile.
__launch_bounds__(256, 2)
__global__ void gemm32_dual_kernel(const __nv_bfloat16* __restrict__ X,
                                   const float* __restrict__ Wl, const float* __restrict__ Wr,
                                   float* __restrict__ Yl, float* __restrict__ Yr) {
    constexpr int S = 68;
    extern __shared__ uint32_t sm[];
    uint32_t* As  = sm;               // [128][68]
    uint32_t* Bls = sm + 128 * S;     // [32][68]
    uint32_t* Brs = Bls + 32 * S;

    const int t = threadIdx.x;
    const int w = t >> 5;
    const int lane = t & 31;
    const int g = lane >> 2, tg = lane & 3;
    const int m0 = blockIdx.x * 128;

#pragma unroll
    for (int it = 0; it < 8; ++it) {
        int idx = t + it * 256;         // 2048 uint4 slots
        int row = idx >> 4, q = idx & 15;
        int gr  = m0 + row;
        uint4 v = make_uint4(0, 0, 0, 0);
        if (gr < N_NODES) v = ((const uint4*)X)[(size_t)gr * 16 + q];
        *(uint4*)(As + row * S + q * 4) = v;
    }
#pragma unroll
    for (int it = 0; it < 8; ++it) {
        int i = t + it * 256;           // 2048 slots
        int kp = i >> 5, n = i & 31;
        Bls[n * S + kp] = pack_bf16(Wl[(2 * kp) * 32 + n], Wl[(2 * kp + 1) * 32 + n]);
        Brs[n * S + kp] = pack_bf16(Wr[(2 * kp) * 32 + n], Wr[(2 * kp + 1) * 32 + n]);
    }
    __syncthreads();

    const int mr = w * 16;
    float accl[4][4], accr[4][4];
#pragma unroll
    for (int n = 0; n < 4; ++n)
#pragma unroll
        for (int q = 0; q < 4; ++q) { accl[n][q] = 0.f; accr[n][q] = 0.f; }

#pragma unroll
    for (int kt = 0; kt < 8; ++kt) {
        const int kb = kt * 8;
        uint32_t a[4];
        a[0] = As[(mr + g)     * S + kb + tg];
        a[1] = As[(mr + g + 8) * S + kb + tg];
        a[2] = As[(mr + g)     * S + kb + tg + 4];
        a[3] = As[(mr + g + 8) * S + kb + tg + 4];
#pragma unroll
        for (int n = 0; n < 4; ++n) {
            int col = n * 8 + g;
            uint32_t bl[2], br[2];
            bl[0] = Bls[col * S + kb + tg];
            bl[1] = Bls[col * S + kb + tg + 4];
            br[0] = Brs[col * S + kb + tg];
            br[1] = Brs[col * S + kb + tg + 4];
            mma_bf16(accl[n], a, bl);
            mma_bf16(accr[n], a, br);
        }
    }

    const int r0 = m0 + mr + g;
    const int r1 = r0 + 8;
#pragma unroll
    for (int n = 0; n < 4; ++n) {
        int col = n * 8 + 2 * tg;
        if (r0 < N_NODES) {
            *(float2*)(Yl + (size_t)r0 * 32 + col) = make_float2(accl[n][0], accl[n][1]);
            *(float2*)(Yr + (size_t)r0 * 32 + col) = make_float2(accr[n][0], accr[n][1]);
        }
        if (r1 < N_NODES) {
            *(float2*)(Yl + (size_t)r1 * 32 + col) = make_float2(accl[n][2], accl[n][3]);
            *(float2*)(Yr + (size_t)r1 * 32 + col) = make_float2(accr[n][2], accr[n][3]);
        }
    }
}

// ---------------- aggregation (CSR gather, bf16) + relu epilogue, bf16 output ----------------
__global__ void agg_relu_kernel(const __nv_bfloat16* __restrict__ ylb, const float* __restrict__ yr,
                                const float* __restrict__ bl, __nv_bfloat16* __restrict__ hb) {
    int node = blockIdx.x * (blockDim.x >> 5) + (threadIdx.x >> 5);
    if (node >= N_NODES) return;
    int lane = threadIdx.x & 31;
    int beg = g_rowptr[node], end = g_rowptr[node + 1];
    float a0 = 0.f, a1 = 0.f, a2 = 0.f, a3 = 0.f;
    int j = beg;
    for (; j + 4 <= end; j += 4) {
        int s0 = __ldg(&g_srcs[j]);
        int s1 = __ldg(&g_srcs[j + 1]);
        int s2 = __ldg(&g_srcs[j + 2]);
        int s3 = __ldg(&g_srcs[j + 3]);
        uint2 u0 = *(const uint2*)((const char*)ylb + (size_t)s0 * 256 + lane * 8);
        uint2 u1 = *(const uint2*)((const char*)ylb + (size_t)s1 * 256 + lane * 8);
        uint2 u2 = *(const uint2*)((const char*)ylb + (size_t)s2 * 256 + lane * 8);
        uint2 u3 = *(const uint2*)((const char*)ylb + (size_t)s3 * 256 + lane * 8);
        float2 f;
        f = __bfloat1622float2(*(__nv_bfloat162*)&u0.x); a0 += f.x; a1 += f.y;
        f = __bfloat1622float2(*(__nv_bfloat162*)&u0.y); a2 += f.x; a3 += f.y;
        f = __bfloat1622float2(*(__nv_bfloat162*)&u1.x); a0 += f.x; a1 += f.y;
        f = __bfloat1622float2(*(__nv_bfloat162*)&u1.y); a2 += f.x; a3 += f.y;
        f = __bfloat1622float2(*(__nv_bfloat162*)&u2.x); a0 += f.x; a1 += f.y;
        f = __bfloat1622float2(*(__nv_bfloat162*)&u2.y); a2 += f.x; a3 += f.y;
        f = __bfloat1622float2(*(__nv_bfloat162*)&u3.x); a0 += f.x; a1 += f.y;
        f = __bfloat1622float2(*(__nv_bfloat162*)&u3.y); a2 += f.x; a3 += f.y;
    }
    for (; j < end; ++j) {
        int s = __ldg(&g_srcs[j]);
        uint2 u = *(const uint2*)((const char*)ylb + (size_t)s * 256 + lane * 8);
        float2 f0 = __bfloat1622float2(*(__nv_bfloat162*)&u.x);
        float2 f1 = __bfloat1622float2(*(__nv_bfloat162*)&u.y);
        a0 += f0.x; a1 += f0.y; a2 += f1.x; a3 += f1.y;
    }
    float id = g_invdeg[node];
    float4 r = ((const float4*)yr)[(size_t)node * 32 + lane];
    float4 b = ((const float4*)bl)[lane];
    float o0 = fmaxf(fmaf(a0, id, b.x) + r.x, 0.f);
    float o1 = fmaxf(fmaf(a1, id, b.y) + r.y, 0.f);
    float o2 = fmaxf(fmaf(a2, id, b.z) + r.z, 0.f);
    float o3 = fmaxf(fmaf(a3, id, b.w) + r.w, 0.f);
    uint2 ov = make_uint2(pack_bf16(o0, o1), pack_bf16(o2, o3));
    *(uint2*)((char*)hb + (size_t)node * 256 + lane * 8) = ov;
}

// out = log_softmax(mean_gather(yl fp32) + bl2 + yr); one warp per node
__global__ void agg_lsm_kernel(const float* __restrict__ yl, const float* __restrict__ yr,
                               const float* __restrict__ bl2, float* __restrict__ out) {
    int node = blockIdx.x * (blockDim.x >> 5) + (threadIdx.x >> 5);
    if (node >= N_NODES) return;
    int lane = threadIdx.x & 31;
    int beg = g_rowptr[node], end = g_rowptr[node + 1];
    float acc = 0.f;
    int j = beg;
    for (; j + 4 <= end; j += 4) {
        int s0 = __ldg(&g_srcs[j]);
        int s1 = __ldg(&g_srcs[j + 1]);
        int s2 = __ldg(&g_srcs[j + 2]);
        int s3 = __ldg(&g_srcs[j + 3]);
        acc += __ldg(yl + (size_t)s0 * 32 + lane) + __ldg(yl + (size_t)s1 * 32 + lane)
             + __ldg(yl + (size_t)s2 * 32 + lane) + __ldg(yl + (size_t)s3 * 32 + lane);
    }
    for (; j < end; ++j) acc += __ldg(yl + (size_t)__ldg(&g_srcs[j]) * 32 + lane);
    float v = fmaf(acc, g_invdeg[node], bl2[lane]) + yr[(size_t)node * 32 + lane];
    float m = v;
#pragma unroll
    for (int o = 16; o; o >>= 1) m = fmaxf(m, __shfl_xor_sync(0xFFFFFFFFu, m, o));
    float ex = expf(v - m);
    float s = ex;
#pragma unroll
    for (int o = 16; o; o >>= 1) s += __shfl_xor_sync(0xFFFFFFFFu, s, o);
    out[(size_t)node * 32 + lane] = v - m - logf(s);
}

// ---------------- host ----------------
extern "C" void kernel_launch(void* const* d_in, const int* in_sizes, int n_in,
                              void* d_out, int out_size) {
    const float* x   = (const float*)d_in[0];
    const void*  ei  = d_in[1];
    const float* Wl0 = (const float*)d_in[2];
    const float* bl0 = (const float*)d_in[3];
    const float* Wr0 = (const float*)d_in[4];
    const float* Wl1 = (const float*)d_in[5];
    const float* bl1 = (const float*)d_in[6];
    const float* Wr1 = (const float*)d_in[7];
    const float* Wl2 = (const float*)d_in[8];
    const float* bl2 = (const float*)d_in[9];
    const float* Wr2 = (const float*)d_in[10];
    float* out = (float*)d_out;

    float *yl, *yr, *h0;
    cudaGetSymbolAddress((void**)&yl, g_yl);
    cudaGetSymbolAddress((void**)&yr, g_yr);
    cudaGetSymbolAddress((void**)&h0, g_h0);
    __nv_bfloat16* ylb = (__nv_bfloat16*)yl;
    __nv_bfloat16* h0b = (__nv_bfloat16*)h0;

    static cudaStream_t s2 = nullptr;
    static cudaEvent_t ev_fork = nullptr, ev_join = nullptr;
    if (!s2) {
        cudaStreamCreateWithFlags(&s2, cudaStreamNonBlocking);
        cudaEventCreateWithFlags(&ev_fork, cudaEventDisableTiming);
        cudaEventCreateWithFlags(&ev_join, cudaEventDisableTiming);
    }

    const int SMEM128 = 3 * 128 * 68 * 4;                 // 104448
    const int SMEM32  = (128 * 68 + 2 * 32 * 68) * 4;     // 52224
    cudaFuncSetAttribute(gemm128_dual_kernel<float>, cudaFuncAttributeMaxDynamicSharedMemorySize, SMEM128);
    cudaFuncSetAttribute(gemm128_dual_kernel<__nv_bfloat16>, cudaFuncAttributeMaxDynamicSharedMemorySize, SMEM128);
    cudaFuncSetAttribute(gemm32_dual_kernel, cudaFuncAttributeMaxDynamicSharedMemorySize, SMEM32);

    const int T = 256;
    const int NB = (N_NODES + T - 1) / T;
    const int EB = (N_EDGES + T - 1) / T;
    const int SCB = (N_NODES + SCAN_B - 1) / SCAN_B;
    const int AGG_B = (N_NODES + 7) / 8;
    const int GT = (N_NODES + 127) / 128;

    // ---- fork: CSR build on s2, layer-0 GEMM on main stream ----
    cudaEventRecord(ev_fork, 0);
    cudaStreamWaitEvent(s2, ev_fork, 0);

    detect_idx_kernel<<<1, 32, 0, s2>>>((const int*)ei);
    zero_cnt_kernel<<<NB, T, 0, s2>>>();
    hist_kernel<<<EB, T, 0, s2>>>(ei);
    scan_block_kernel<<<SCB, SCAN_B, 0, s2>>>();
    scan_bsum_kernel<<<1, 32, 0, s2>>>(SCB);
    finalize_csr_kernel<<<NB, T, 0, s2>>>();
    fill_kernel<<<EB, T, 0, s2>>>(ei);
    cudaEventRecord(ev_join, s2);

    gemm128_dual_kernel<float><<<GT, 512, SMEM128>>>(x, Wl0, Wr0, ylb, yr);

    cudaStreamWaitEvent(0, ev_join, 0);   // join before aggregation

    // ---- Layer 0 aggregation ----
    agg_relu_kernel<<<AGG_B, T>>>(ylb, yr, bl0, h0b);
    // ---- Layer 1 ----
    gemm128_dual_kernel<__nv_bfloat16><<<GT, 512, SMEM128>>>(h0b, Wl1, Wr1, ylb, yr);
    agg_relu_kernel<<<AGG_B, T>>>(ylb, yr, bl1, h0b);
    // ---- Layer 2 ----
    gemm32_dual_kernel<<<GT, T, SMEM32>>>(h0b, Wl2, Wr2, yl, yr);
    agg_lsm_kernel<<<AGG_B, T>>>(yl, yr, bl2, out);
}